// round 15
// baseline (speedup 1.0000x reference)
#include <cuda_runtime.h>
#include <cuda_fp16.h>
#include <math.h>
#include <stdint.h>

#define D 128
#define NSTAGE 6

// ===================== device globals =====================
__device__ __align__(128) __half d_Gpack[NSTAGE][D * D]; // G_m fp16, paired-B-fragment pack
__device__ float d_au0x[D], d_au0t[D];
__device__ float d_vfin[D];

// ===================== helpers =====================
__device__ __forceinline__ uint32_t smem_u32(const void* p) {
    uint32_t a;
    asm("{ .reg .u64 t; cvta.to.shared.u64 t, %1; cvt.u32.u64 %0, t; }" : "=r"(a) : "l"(p));
    return a;
}
__device__ __forceinline__ float tanh_ap(float x) {
    float y; asm("tanh.approx.f32 %0, %1;" : "=f"(y) : "f"(x)); return y;
}
__device__ __forceinline__ float sigmoid_fast(float x) {
    return fmaf(tanh_ap(0.5f * x), 0.5f, 0.5f);
}
// packed sigmoid: inputs are PRE-HALVED z = 0.5*(c + bias); returns half2 {lo,hi} bits
__device__ __forceinline__ float sig16x2(float zlo, float zhi) {
    uint32_t h, t, r;
    asm("cvt.rn.f16x2.f32 %0, %1, %2;" : "=r"(h) : "f"(zhi), "f"(zlo));
    asm("tanh.approx.f16x2 %0, %1;" : "=r"(t) : "r"(h));
    const uint32_t half05 = 0x38003800u;   // half2{0.5, 0.5}
    asm("fma.rn.f16x2 %0, %1, %2, %2;" : "=r"(r) : "r"(t), "r"(half05));
    return __uint_as_float(r);
}

#define MBARRIER_INIT(mbar, count) \
    asm volatile("mbarrier.init.shared.b64 [%0], %1;" :: "r"((uint32_t)(mbar)), "r"((uint32_t)(count)) : "memory")
#define MBARRIER_ARRIVE(mbar) \
    asm volatile("mbarrier.arrive.shared.b64 _, [%0];" :: "r"((uint32_t)(mbar)) : "memory")
#define MBARRIER_EXPECT_TX(mbar, bytes) \
    asm volatile("mbarrier.arrive.expect_tx.shared.b64 _, [%0], %1;" :: "r"((uint32_t)(mbar)), "r"((uint32_t)(bytes)) : "memory")
#define MBARRIER_WAIT_PARITY(mbar, parity) do { \
    uint32_t _m = (uint32_t)(mbar); uint32_t _p = (uint32_t)(parity); uint32_t _d; \
    asm volatile("{\n\t.reg .pred p;\n\t" \
        "mbarrier.try_wait.parity.acquire.cta.shared::cta.b64 p, [%1], %2;\n\t" \
        "selp.b32 %0, 1, 0, p;\n\t}" : "=r"(_d) : "r"(_m), "r"(_p) : "memory"); \
    if (!_d) { \
        asm volatile("{\n\t.reg .pred P1;\n\t" \
            "WAIT_LOOP_%=:\n\t" \
            "mbarrier.try_wait.parity.acquire.cta.shared::cta.b64 P1, [%0], %1, 0x989680;\n\t" \
            "@P1 bra.uni WAIT_DONE_%=;\n\t" \
            "bra.uni WAIT_LOOP_%=;\n\t" \
            "WAIT_DONE_%=:\n\t}" :: "r"(_m), "r"(_p) : "memory"); \
    } \
} while (0)

#define BULK_G2S(smem, gptr, bytes, mbar) \
    asm volatile("cp.async.bulk.shared::cluster.global.mbarrier::complete_tx::bytes [%0], [%1], %2, [%3];" \
        :: "r"((uint32_t)(smem)), "l"(gptr), "r"((uint32_t)(bytes)), "r"((uint32_t)(mbar)) : "memory")

#define PAIR_BAR(id) \
    asm volatile("bar.sync %0, 64;" :: "r"(id) : "memory")

// mma.sync m16n8k16 fp16 -> fp32 accum
__device__ __forceinline__ void mma16(float* d, const float4 a, float b0, float b1) {
    asm volatile(
        "mma.sync.aligned.m16n8k16.row.col.f32.f16.f16.f32 "
        "{%0,%1,%2,%3}, {%4,%5,%6,%7}, {%8,%9}, {%0,%1,%2,%3};"
        : "+f"(d[0]), "+f"(d[1]), "+f"(d[2]), "+f"(d[3])
        : "r"(__float_as_uint(a.x)), "r"(__float_as_uint(a.y)),
          "r"(__float_as_uint(a.z)), "r"(__float_as_uint(a.w)),
          "r"(__float_as_uint(b0)), "r"(__float_as_uint(b1)));
}

// ===================== warp softmax over a 128-row (fast exp; weights are fp16-bound) ====
__device__ __forceinline__ void warp_softmax_row(const float* __restrict__ row,
                                                 float* __restrict__ dst,
                                                 float scale, int lane) {
    float v[4];
#pragma unroll
    for (int q = 0; q < 4; q++) v[q] = row[lane + 32 * q];
    float m = fmaxf(fmaxf(v[0], v[1]), fmaxf(v[2], v[3]));
#pragma unroll
    for (int o = 16; o > 0; o >>= 1) m = fmaxf(m, __shfl_xor_sync(~0u, m, o));
    float e[4]; float s = 0.f;
#pragma unroll
    for (int q = 0; q < 4; q++) { e[q] = __expf(v[q] - m); s += e[q]; }
#pragma unroll
    for (int o = 16; o > 0; o >>= 1) s += __shfl_xor_sync(~0u, s, o);
    const float inv = scale / s;
#pragma unroll
    for (int q = 0; q < 4; q++) dst[lane + 32 * q] = e[q] * inv;
}

// ===================== single prep kernel =====================
__global__ void __launch_bounds__(256) prep_kernel(
    const float* __restrict__ u0, const float* __restrict__ w0,
    const float* __restrict__ la0,
    const float* __restrict__ uM, const float* __restrict__ wM,
    const float* __restrict__ laM,
    const float* __restrict__ uL, const float* __restrict__ laL) {
    extern __shared__ float sh[];   // sW 16384 | sAU 2048
    float* sW = sh;
    float* sAU = sh + 16384;
    const int b = blockIdx.x, tid = threadIdx.x;
    const int w = tid >> 5, lane = tid & 31;

    if (b < 48) {
        const int m = b >> 3;
        const int oc = (b & 7) * 16;
        const float* wsrc = (m == 0) ? w0 : (wM + (m - 1) * D * D);
#pragma unroll 1
        for (int r = w; r < 128; r += 8)
            warp_softmax_row(wsrc + r * D, sW + r * D, 1.0f, lane);
#pragma unroll 1
        for (int rl = w; rl < 16; rl += 8) {
            const int o = oc + rl;
            warp_softmax_row(uM + (m * D + o) * D, sAU + rl * D, __expf(laM[m * D + o]), lane);
        }
        __syncthreads();
#pragma unroll 1
        for (int q = 0; q < 8; q++) {
            const int idx = tid + q * 256;
            const int ol = idx >> 7, i = idx & 127;
            const float* au = sAU + ol * D;
            float acc = 0.f;
#pragma unroll 8
            for (int j = 0; j < D; j++) acc = fmaf(au[j], sW[j * D + i], acc);
            const int o = oc + ol;
            const int t = o >> 3, g = o & 7;
            const int kp = i >> 4, o16 = i & 15;
            const int breg = o16 >> 3, tg = (o16 >> 1) & 3, hl = i & 1;
            const int G = t * 8 + kp;
            const int P = G >> 1, S = G & 1;
            const int L = g * 4 + tg;
            const int hidx = (P * 32 + L) * 8 + S * 4 + breg * 2 + hl;
            d_Gpack[m][hidx] = __float2half_rn(acc);
        }
    } else if (b == 48) {
#pragma unroll 1
        for (int r = w; r < 128; r += 8)
            warp_softmax_row(wM + 5 * D * D + r * D, sW + r * D, 1.0f, lane);
        if (w == 0) warp_softmax_row(uL, sAU, __expf(laL[0]), lane);
        __syncthreads();
        if (tid < D) {
            float acc = 0.f;
#pragma unroll 8
            for (int j = 0; j < D; j++) acc = fmaf(sAU[j], sW[j * D + tid], acc);
            d_vfin[tid] = acc;
        }
    } else {
        if (tid < D) {
            const int o = tid;
            float v0 = u0[o * 2 + 0], v1 = u0[o * 2 + 1];
            float m = fmaxf(v0, v1);
            float e0 = __expf(v0 - m), e1 = __expf(v1 - m);
            float inv = __expf(la0[o]) / (e0 + e1);
            d_au0x[o] = e0 * inv;
            d_au0t[o] = e1 * inv;
        }
    }
}

// ===================== fused kernel =====================
// 256 threads, 8 warps (wm=w>>1 -> rows wm*32..+32; wn=w&1 -> cols wn*64..+64).
// Pair barriers + full/empty mbarrier weight ring. NEW: each warp retains its OWN
// half of next-stage A-fragments (kp = 4wn..4wn+3, both m-tiles) in registers;
// only the peer half goes through SMEM. Biases for stages 0..4 stored PRE-HALVED.
// dyn floats: [0,8192) Apack; [8192,16384) wbuf0; [16384,24576) wbuf1.
__global__ void __launch_bounds__(256, 2) fused_kernel(
    const float* __restrict__ x, const float* __restrict__ fy0,
    const float* __restrict__ b0g, const float* __restrict__ bMg,
    const float* __restrict__ bLg,
    const float* __restrict__ W1, const float* __restrict__ b1,
    const float* __restrict__ W2, const float* __restrict__ b2,
    const float* __restrict__ W3, const float* __restrict__ b3,
    float* __restrict__ out, int n) {
    extern __shared__ float dyn[];
    __shared__ __align__(16) float s_c[1281];     // au0x|au0t|b0|hbM[0..4]|bM5|v|bL
    __shared__ float s_x[128], s_fy[128], s_th[128];
    __shared__ float s_fin[256];
    __shared__ __align__(8) unsigned long long s_bar[4];  // full0, full1, empty0, empty1

    const int tid = threadIdx.x;
    const int w = tid >> 5, lane = tid & 31;
    const int g = lane >> 2, tig = lane & 3;
    const int wm = w >> 1, wn = w & 1;
    const int barid = 1 + wm;
    const uint32_t mbF0 = smem_u32(&s_bar[0]);
    const uint32_t mbF1 = smem_u32(&s_bar[1]);
    const uint32_t mbE0 = smem_u32(&s_bar[2]);
    const uint32_t mbE1 = smem_u32(&s_bar[3]);
    const uint32_t dynb = smem_u32(dyn);

    float4* a4 = (float4*)dyn;      // 2048 float4 = 32KB Apack
    float* s_mlp = dyn;             // MLP weights borrow Apack region before stage 0

    if (tid == 0) {
        MBARRIER_INIT(mbF0, 1); MBARRIER_INIT(mbF1, 1);
        MBARRIER_INIT(mbE0, 8); MBARRIER_INIT(mbE1, 8);
        MBARRIER_EXPECT_TX(mbF0, 32768);
        BULK_G2S(dynb + 32768u, &d_Gpack[0][0], 32768, mbF0);
        MBARRIER_EXPECT_TX(mbF1, 32768);
        BULK_G2S(dynb + 65536u, &d_Gpack[1][0], 32768, mbF1);
        s_c[1280] = bLg[0];
    }
    {
        const int gi = blockIdx.x * 128 + tid;
        if (tid < 128) {
            const bool ok = gi < n;
            s_x[tid] = ok ? x[gi] : 0.f;
            s_fy[tid] = ok ? fy0[gi] : 0.f;
            s_c[tid] = d_au0x[tid];
            s_c[128 + tid] = d_au0t[tid];
            s_c[256 + tid] = b0g[tid];
#pragma unroll
            for (int m = 0; m < 5; m++) s_c[384 + m * 128 + tid] = 0.5f * bMg[m * 128 + tid];
            s_c[384 + 5 * 128 + tid] = bMg[5 * 128 + tid];   // final stage: full bias
            s_c[1152 + tid] = d_vfin[tid];
        }
        if (tid < 50) {
            s_mlp[tid] = W1[tid]; s_mlp[50 + tid] = b1[tid];
            s_mlp[100 + tid] = b2[tid]; s_mlp[150 + tid] = W3[tid];
        }
        if (tid == 0) s_mlp[2804] = b3[0];
        for (int i = tid; i < 2500; i += 256) {
            const int row = i / 50, col = i % 50;
            s_mlp[200 + row * 52 + col] = W2[i];
        }
        if (tid < 100) s_mlp[200 + (tid >> 1) * 52 + 50 + (tid & 1)] = 0.f;
    }
    __syncthreads();

    // ---- theta MLP: 2 threads per row, float4 W2 reads ----
    {
        const int rl = tid >> 1, hf = tid & 1;
        const float fv = s_fy[rl];
        float h1[52];
        h1[50] = 0.f; h1[51] = 0.f;
#pragma unroll
        for (int j = 0; j < 50; j++) h1[j] = fmaxf(fmaf(s_mlp[j], fv, s_mlp[50 + j]), 0.f);
        float part = 0.f;
        const int j0 = hf * 25;
#pragma unroll 1
        for (int j = j0; j < j0 + 25; j++) {
            const float4* wr = (const float4*)(s_mlp + 200 + j * 52);
            float a0 = s_mlp[100 + j], a1 = 0.f, a2 = 0.f, a3 = 0.f;
#pragma unroll
            for (int k = 0; k < 13; k++) {
                const float4 t4 = wr[k];
                a0 = fmaf(t4.x, h1[4 * k + 0], a0);
                a1 = fmaf(t4.y, h1[4 * k + 1], a1);
                a2 = fmaf(t4.z, h1[4 * k + 2], a2);
                a3 = fmaf(t4.w, h1[4 * k + 3], a3);
            }
            part = fmaf(s_mlp[150 + j], fmaxf((a0 + a1) + (a2 + a3), 0.f), part);
        }
        part += __shfl_xor_sync(~0u, part, 1);
        if (hf == 0) s_th[rl] = part + s_mlp[2804];
    }
    __syncthreads();   // theta done; Apack region free

    // ---- first layer: t0 -> Apack (warp w owns m-tile w) ----
    {
        const int l0 = w * 16 + g, l1 = l0 + 8;
        const float x0 = s_x[l0], x1 = s_x[l1];
        const float t0v = s_th[l0], t1v = s_th[l1];
#pragma unroll
        for (int kp = 0; kp < 8; kp++) {
            const int k0 = kp * 16 + 2 * tig;
            const int k8 = k0 + 8;
            float4 v;
            v.x = sig16x2(0.5f * fmaf(x0, s_c[k0], fmaf(t0v, s_c[128 + k0], s_c[256 + k0])),
                          0.5f * fmaf(x0, s_c[k0 + 1], fmaf(t0v, s_c[128 + k0 + 1], s_c[256 + k0 + 1])));
            v.y = sig16x2(0.5f * fmaf(x1, s_c[k0], fmaf(t1v, s_c[128 + k0], s_c[256 + k0])),
                          0.5f * fmaf(x1, s_c[k0 + 1], fmaf(t1v, s_c[128 + k0 + 1], s_c[256 + k0 + 1])));
            v.z = sig16x2(0.5f * fmaf(x0, s_c[k8], fmaf(t0v, s_c[128 + k8], s_c[256 + k8])),
                          0.5f * fmaf(x0, s_c[k8 + 1], fmaf(t0v, s_c[128 + k8 + 1], s_c[256 + k8 + 1])));
            v.w = sig16x2(0.5f * fmaf(x1, s_c[k8], fmaf(t1v, s_c[128 + k8], s_c[256 + k8])),
                          0.5f * fmaf(x1, s_c[k8 + 1], fmaf(t1v, s_c[128 + k8 + 1], s_c[256 + k8 + 1])));
            a4[(w * 8 + kp) * 32 + lane] = v;
        }
    }
    PAIR_BAR(barid);

    const int mt0 = wm * 2, mt1 = mt0 + 1;

    // ---- load own-half A fragments into registers (kp = 4wn..4wn+3, both m-tiles) ----
    float4 Aown[2][4];
#pragma unroll
    for (int tm = 0; tm < 2; tm++)
#pragma unroll
        for (int q = 0; q < 4; q++)
            Aown[tm][q] = a4[((mt0 + tm) * 8 + wn * 4 + q) * 32 + lane];

    // ---- 6 GEMM stages ----
#pragma unroll 1
    for (int s = 0; s < NSTAGE; s++) {
        const uint32_t mbF = (s & 1) ? mbF1 : mbF0;
        const uint32_t mbE = (s & 1) ? mbE1 : mbE0;
        const int par = (s >> 1) & 1;
        MBARRIER_WAIT_PARITY(mbF, par);

        float Cacc[2][8][4];
#pragma unroll
        for (int tm = 0; tm < 2; tm++)
#pragma unroll
            for (int t = 0; t < 8; t++) {
                Cacc[tm][t][0] = 0.f; Cacc[tm][t][1] = 0.f;
                Cacc[tm][t][2] = 0.f; Cacc[tm][t][3] = 0.f;
            }

        const float4* wb4 = (const float4*)(dyn + 8192 + (s & 1) * 8192);
        // own half: A from registers (no LDS, no latency at stage start)
#pragma unroll
        for (int qq = 0; qq < 2; qq++) {
            const int kph = wn * 2 + qq;
#pragma unroll
            for (int tll = 0; tll < 8; tll++) {
                const float4 bf = wb4[(((wn * 8 + tll) * 4 + kph) * 32) + lane];
                mma16(Cacc[0][tll], Aown[0][2 * qq], bf.x, bf.y);
                mma16(Cacc[0][tll], Aown[0][2 * qq + 1], bf.z, bf.w);
                mma16(Cacc[1][tll], Aown[1][2 * qq], bf.x, bf.y);
                mma16(Cacc[1][tll], Aown[1][2 * qq + 1], bf.z, bf.w);
            }
        }
        // peer half: A from SMEM
#pragma unroll
        for (int qq = 0; qq < 2; qq++) {
            const int kph = (1 - wn) * 2 + qq;
            const float4 A0a = a4[(mt0 * 8 + 2 * kph) * 32 + lane];
            const float4 A0b = a4[(mt0 * 8 + 2 * kph + 1) * 32 + lane];
            const float4 A1a = a4[(mt1 * 8 + 2 * kph) * 32 + lane];
            const float4 A1b = a4[(mt1 * 8 + 2 * kph + 1) * 32 + lane];
#pragma unroll
            for (int tll = 0; tll < 8; tll++) {
                const float4 bf = wb4[(((wn * 8 + tll) * 4 + kph) * 32) + lane];
                mma16(Cacc[0][tll], A0a, bf.x, bf.y);
                mma16(Cacc[0][tll], A0b, bf.z, bf.w);
                mma16(Cacc[1][tll], A1a, bf.x, bf.y);
                mma16(Cacc[1][tll], A1b, bf.z, bf.w);
            }
        }
        if (lane == 0) MBARRIER_ARRIVE(mbE);

        if (s < NSTAGE - 1) {
            PAIR_BAR(barid);   // peer done reading old Apack
            const float* hb = s_c + 384 + s * 128;   // PRE-HALVED biases (stages 0..4)
#pragma unroll
            for (int tm = 0; tm < 2; tm++) {
                const int mt = mt0 + tm;
#pragma unroll
                for (int q = 0; q < 4; q++) {
                    const int kp = wn * 4 + q;
                    const int n0 = kp * 16 + 2 * tig;
                    const int n1 = n0 + 8;
                    const float hb0 = hb[n0], hb1 = hb[n0 + 1];
                    const float hb2 = hb[n1], hb3 = hb[n1 + 1];
                    float4 v;
                    v.x = sig16x2(fmaf(Cacc[tm][2 * q][0], 0.5f, hb0), fmaf(Cacc[tm][2 * q][1], 0.5f, hb1));
                    v.y = sig16x2(fmaf(Cacc[tm][2 * q][2], 0.5f, hb0), fmaf(Cacc[tm][2 * q][3], 0.5f, hb1));
                    v.z = sig16x2(fmaf(Cacc[tm][2 * q + 1][0], 0.5f, hb2), fmaf(Cacc[tm][2 * q + 1][1], 0.5f, hb3));
                    v.w = sig16x2(fmaf(Cacc[tm][2 * q + 1][2], 0.5f, hb2), fmaf(Cacc[tm][2 * q + 1][3], 0.5f, hb3));
                    Aown[tm][q] = v;                       // retain own half
                    a4[(mt * 8 + kp) * 32 + lane] = v;     // publish for peer
                }
            }
            if (tid == 0 && s < NSTAGE - 2) {
                MBARRIER_WAIT_PARITY(mbE, par);
                MBARRIER_EXPECT_TX(mbF, 32768);
                BULK_G2S(dynb + 32768u + (uint32_t)(s & 1) * 32768u, &d_Gpack[s + 2][0], 32768, mbF);
            }
            PAIR_BAR(barid);   // new Apack visible to peer
        } else {
            const float* bias = s_c + 384 + 5 * 128;   // full bias
            float p[2][2];
            p[0][0] = p[0][1] = p[1][0] = p[1][1] = 0.f;
#pragma unroll
            for (int tm = 0; tm < 2; tm++)
#pragma unroll
                for (int t = 0; t < 8; t++) {
                    const int n0 = wn * 64 + t * 8 + 2 * tig;
                    const float b0v = bias[n0], b1v = bias[n0 + 1];
                    const float v0 = s_c[1152 + n0], v1 = s_c[1152 + n0 + 1];
                    p[tm][0] = fmaf(sigmoid_fast(Cacc[tm][t][0] + b0v), v0, p[tm][0]);
                    p[tm][0] = fmaf(sigmoid_fast(Cacc[tm][t][1] + b1v), v1, p[tm][0]);
                    p[tm][1] = fmaf(sigmoid_fast(Cacc[tm][t][2] + b0v), v0, p[tm][1]);
                    p[tm][1] = fmaf(sigmoid_fast(Cacc[tm][t][3] + b1v), v1, p[tm][1]);
                }
#pragma unroll
            for (int tm = 0; tm < 2; tm++) {
#pragma unroll
                for (int rr = 0; rr < 2; rr++) {
                    p[tm][rr] += __shfl_xor_sync(~0u, p[tm][rr], 1);
                    p[tm][rr] += __shfl_xor_sync(~0u, p[tm][rr], 2);
                }
                if (tig == 0) {
                    const int lr = wm * 32 + tm * 16 + g;
                    s_fin[wn * 128 + lr] = p[tm][0];
                    s_fin[wn * 128 + lr + 8] = p[tm][1];
                }
            }
            __syncthreads();
            if (tid < 128) {
                const int R = blockIdx.x * 128 + tid;
                if (R < n) {
                    const float z = s_fin[tid] + s_fin[128 + tid] + s_c[1280];
                    out[R] = __fdividef(1.0f, 1.0f + __expf(-z));
                }
            }
        }
    }
}

// ===================== launch =====================
extern "C" void kernel_launch(void* const* d_in, const int* in_sizes, int n_in,
                              void* d_out, int out_size) {
    const float* x   = (const float*)d_in[0];
    const float* fy0 = (const float*)d_in[1];
    const float* u0  = (const float*)d_in[2];
    const float* w0  = (const float*)d_in[3];
    const float* la0 = (const float*)d_in[4];
    const float* b0  = (const float*)d_in[5];
    const float* uM  = (const float*)d_in[6];
    const float* wM  = (const float*)d_in[7];
    const float* laM = (const float*)d_in[8];
    const float* bM  = (const float*)d_in[9];
    const float* uL  = (const float*)d_in[10];
    // d_in[11] = wL: softmax of a [1,1] row == 1.0 (identity)
    const float* laL = (const float*)d_in[12];
    const float* bL  = (const float*)d_in[13];
    const float* W1  = (const float*)d_in[14];
    const float* b1  = (const float*)d_in[15];
    const float* W2  = (const float*)d_in[16];
    const float* b2  = (const float*)d_in[17];
    const float* W3  = (const float*)d_in[18];
    const float* b3  = (const float*)d_in[19];
    float* out = (float*)d_out;
    const int n = in_sizes[0];

    const int prep_smem = (16384 + 2048) * 4;   // 73728
    const int fused_smem = 24576 * 4;           // 98304: 32KB Apack + 2x32KB wbuf
    cudaFuncSetAttribute(prep_kernel, cudaFuncAttributeMaxDynamicSharedMemorySize, prep_smem);
    cudaFuncSetAttribute(fused_kernel, cudaFuncAttributeMaxDynamicSharedMemorySize, fused_smem);

    prep_kernel<<<50, 256, prep_smem>>>(u0, w0, la0, uM, wM, laM, uL, laL);
    fused_kernel<<<(n + 127) / 128, 256, fused_smem>>>(x, fy0, b0, bM, bL,
                                                       W1, b1, W2, b2, W3, b3, out, n);
}

// round 16
// speedup vs baseline: 1.0378x; 1.0378x over previous
#include <cuda_runtime.h>
#include <cuda_fp16.h>
#include <math.h>
#include <stdint.h>

#define D 128
#define NSTAGE 6

// ===================== device globals =====================
__device__ __align__(128) __half d_Gpack[NSTAGE][D * D]; // G_m fp16, paired-B-fragment pack
__device__ float d_au0x[D], d_au0t[D];
__device__ float d_vfin[D];

// ===================== helpers =====================
__device__ __forceinline__ uint32_t smem_u32(const void* p) {
    uint32_t a;
    asm("{ .reg .u64 t; cvta.to.shared.u64 t, %1; cvt.u32.u64 %0, t; }" : "=r"(a) : "l"(p));
    return a;
}
__device__ __forceinline__ float tanh_ap(float x) {
    float y; asm("tanh.approx.f32 %0, %1;" : "=f"(y) : "f"(x)); return y;
}
__device__ __forceinline__ float sigmoid_fast(float x) {
    return fmaf(tanh_ap(0.5f * x), 0.5f, 0.5f);
}
// packed sigmoid: inputs are PRE-HALVED z = 0.5*(c + bias); returns half2 {lo,hi} bits
__device__ __forceinline__ float sig16x2(float zlo, float zhi) {
    uint32_t h, t, r;
    asm("cvt.rn.f16x2.f32 %0, %1, %2;" : "=r"(h) : "f"(zhi), "f"(zlo));
    asm("tanh.approx.f16x2 %0, %1;" : "=r"(t) : "r"(h));
    const uint32_t half05 = 0x38003800u;   // half2{0.5, 0.5}
    asm("fma.rn.f16x2 %0, %1, %2, %2;" : "=r"(r) : "r"(t), "r"(half05));
    return __uint_as_float(r);
}

#define MBARRIER_INIT(mbar, count) \
    asm volatile("mbarrier.init.shared.b64 [%0], %1;" :: "r"((uint32_t)(mbar)), "r"((uint32_t)(count)) : "memory")
#define MBARRIER_ARRIVE(mbar) \
    asm volatile("mbarrier.arrive.shared.b64 _, [%0];" :: "r"((uint32_t)(mbar)) : "memory")
#define MBARRIER_EXPECT_TX(mbar, bytes) \
    asm volatile("mbarrier.arrive.expect_tx.shared.b64 _, [%0], %1;" :: "r"((uint32_t)(mbar)), "r"((uint32_t)(bytes)) : "memory")
#define MBARRIER_WAIT_PARITY(mbar, parity) do { \
    uint32_t _m = (uint32_t)(mbar); uint32_t _p = (uint32_t)(parity); uint32_t _d; \
    asm volatile("{\n\t.reg .pred p;\n\t" \
        "mbarrier.try_wait.parity.acquire.cta.shared::cta.b64 p, [%1], %2;\n\t" \
        "selp.b32 %0, 1, 0, p;\n\t}" : "=r"(_d) : "r"(_m), "r"(_p) : "memory"); \
    if (!_d) { \
        asm volatile("{\n\t.reg .pred P1;\n\t" \
            "WAIT_LOOP_%=:\n\t" \
            "mbarrier.try_wait.parity.acquire.cta.shared::cta.b64 P1, [%0], %1, 0x989680;\n\t" \
            "@P1 bra.uni WAIT_DONE_%=;\n\t" \
            "bra.uni WAIT_LOOP_%=;\n\t" \
            "WAIT_DONE_%=:\n\t}" :: "r"(_m), "r"(_p) : "memory"); \
    } \
} while (0)

#define BULK_G2S(smem, gptr, bytes, mbar) \
    asm volatile("cp.async.bulk.shared::cluster.global.mbarrier::complete_tx::bytes [%0], [%1], %2, [%3];" \
        :: "r"((uint32_t)(smem)), "l"(gptr), "r"((uint32_t)(bytes)), "r"((uint32_t)(mbar)) : "memory")

#define PAIR_BAR(id) \
    asm volatile("bar.sync %0, 64;" :: "r"(id) : "memory")

// mma.sync m16n8k16 fp16 -> fp32 accum
__device__ __forceinline__ void mma16(float* d, const float4 a, float b0, float b1) {
    asm volatile(
        "mma.sync.aligned.m16n8k16.row.col.f32.f16.f16.f32 "
        "{%0,%1,%2,%3}, {%4,%5,%6,%7}, {%8,%9}, {%0,%1,%2,%3};"
        : "+f"(d[0]), "+f"(d[1]), "+f"(d[2]), "+f"(d[3])
        : "r"(__float_as_uint(a.x)), "r"(__float_as_uint(a.y)),
          "r"(__float_as_uint(a.z)), "r"(__float_as_uint(a.w)),
          "r"(__float_as_uint(b0)), "r"(__float_as_uint(b1)));
}

// ===================== warp softmax over a 128-row =====================
__device__ __forceinline__ void warp_softmax_row(const float* __restrict__ row,
                                                 float* __restrict__ dst,
                                                 float scale, int lane) {
    float v[4];
#pragma unroll
    for (int q = 0; q < 4; q++) v[q] = row[lane + 32 * q];
    float m = fmaxf(fmaxf(v[0], v[1]), fmaxf(v[2], v[3]));
#pragma unroll
    for (int o = 16; o > 0; o >>= 1) m = fmaxf(m, __shfl_xor_sync(~0u, m, o));
    float e[4]; float s = 0.f;
#pragma unroll
    for (int q = 0; q < 4; q++) { e[q] = __expf(v[q] - m); s += e[q]; }
#pragma unroll
    for (int o = 16; o > 0; o >>= 1) s += __shfl_xor_sync(~0u, s, o);
    const float inv = scale / s;
#pragma unroll
    for (int q = 0; q < 4; q++) dst[lane + 32 * q] = e[q] * inv;
}

// ===================== single prep kernel =====================
__global__ void __launch_bounds__(256) prep_kernel(
    const float* __restrict__ u0, const float* __restrict__ w0,
    const float* __restrict__ la0,
    const float* __restrict__ uM, const float* __restrict__ wM,
    const float* __restrict__ laM,
    const float* __restrict__ uL, const float* __restrict__ laL) {
    extern __shared__ float sh[];   // sW 16384 | sAU 2048
    float* sW = sh;
    float* sAU = sh + 16384;
    const int b = blockIdx.x, tid = threadIdx.x;
    const int w = tid >> 5, lane = tid & 31;

    if (b < 48) {
        const int m = b >> 3;
        const int oc = (b & 7) * 16;
        const float* wsrc = (m == 0) ? w0 : (wM + (m - 1) * D * D);
#pragma unroll 1
        for (int r = w; r < 128; r += 8)
            warp_softmax_row(wsrc + r * D, sW + r * D, 1.0f, lane);
#pragma unroll 1
        for (int rl = w; rl < 16; rl += 8) {
            const int o = oc + rl;
            warp_softmax_row(uM + (m * D + o) * D, sAU + rl * D, __expf(laM[m * D + o]), lane);
        }
        __syncthreads();
#pragma unroll 1
        for (int q = 0; q < 8; q++) {
            const int idx = tid + q * 256;
            const int ol = idx >> 7, i = idx & 127;
            const float* au = sAU + ol * D;
            float acc = 0.f;
#pragma unroll 8
            for (int j = 0; j < D; j++) acc = fmaf(au[j], sW[j * D + i], acc);
            const int o = oc + ol;
            const int t = o >> 3, g = o & 7;
            const int kp = i >> 4, o16 = i & 15;
            const int breg = o16 >> 3, tg = (o16 >> 1) & 3, hl = i & 1;
            const int G = t * 8 + kp;
            const int P = G >> 1, S = G & 1;
            const int L = g * 4 + tg;
            const int hidx = (P * 32 + L) * 8 + S * 4 + breg * 2 + hl;
            d_Gpack[m][hidx] = __float2half_rn(acc);
        }
    } else if (b == 48) {
#pragma unroll 1
        for (int r = w; r < 128; r += 8)
            warp_softmax_row(wM + 5 * D * D + r * D, sW + r * D, 1.0f, lane);
        if (w == 0) warp_softmax_row(uL, sAU, __expf(laL[0]), lane);
        __syncthreads();
        if (tid < D) {
            float acc = 0.f;
#pragma unroll 8
            for (int j = 0; j < D; j++) acc = fmaf(sAU[j], sW[j * D + tid], acc);
            d_vfin[tid] = acc;
        }
    } else {
        if (tid < D) {
            const int o = tid;
            float v0 = u0[o * 2 + 0], v1 = u0[o * 2 + 1];
            float m = fmaxf(v0, v1);
            float e0 = __expf(v0 - m), e1 = __expf(v1 - m);
            float inv = __expf(la0[o]) / (e0 + e1);
            d_au0x[o] = e0 * inv;
            d_au0t[o] = e1 * inv;
        }
    }
}

// ===================== fused kernel =====================
// R14 skeleton (measured 115.2us) with two changes:
//   1. Stage loop FULLY UNROLLED (compile-time s: parities, branches, buffer selects).
//   2. tid0's empty-wait + prefetch moved AFTER the second pair barrier so the
//      all-warps wait no longer blocks warp 1 / the pair's next stage.
// dyn floats: [0,8192) Apack; [8192,16384) wbuf0; [16384,24576) wbuf1.
__global__ void __launch_bounds__(256, 2) fused_kernel(
    const float* __restrict__ x, const float* __restrict__ fy0,
    const float* __restrict__ b0g, const float* __restrict__ bMg,
    const float* __restrict__ bLg,
    const float* __restrict__ W1, const float* __restrict__ b1,
    const float* __restrict__ W2, const float* __restrict__ b2,
    const float* __restrict__ W3, const float* __restrict__ b3,
    float* __restrict__ out, int n) {
    extern __shared__ float dyn[];
    __shared__ __align__(16) float s_c[1281];     // au0x|au0t|b0|bM[6]|v|bL
    __shared__ float s_x[128], s_fy[128], s_th[128];
    __shared__ float s_fin[256];
    __shared__ __align__(8) unsigned long long s_bar[4];  // full0, full1, empty0, empty1

    const int tid = threadIdx.x;
    const int w = tid >> 5, lane = tid & 31;
    const int g = lane >> 2, tig = lane & 3;
    const int wm = w >> 1, wn = w & 1;
    const int barid = 1 + wm;
    const uint32_t mbF0 = smem_u32(&s_bar[0]);
    const uint32_t mbF1 = smem_u32(&s_bar[1]);
    const uint32_t mbE0 = smem_u32(&s_bar[2]);
    const uint32_t mbE1 = smem_u32(&s_bar[3]);
    const uint32_t dynb = smem_u32(dyn);

    float4* a4 = (float4*)dyn;      // 2048 float4 = 32KB Apack
    float* s_mlp = dyn;             // MLP weights borrow Apack region before stage 0

    if (tid == 0) {
        MBARRIER_INIT(mbF0, 1); MBARRIER_INIT(mbF1, 1);
        MBARRIER_INIT(mbE0, 8); MBARRIER_INIT(mbE1, 8);
        MBARRIER_EXPECT_TX(mbF0, 32768);
        BULK_G2S(dynb + 32768u, &d_Gpack[0][0], 32768, mbF0);
        MBARRIER_EXPECT_TX(mbF1, 32768);
        BULK_G2S(dynb + 65536u, &d_Gpack[1][0], 32768, mbF1);
        s_c[1280] = bLg[0];
    }
    {
        const int gi = blockIdx.x * 128 + tid;
        if (tid < 128) {
            const bool ok = gi < n;
            s_x[tid] = ok ? x[gi] : 0.f;
            s_fy[tid] = ok ? fy0[gi] : 0.f;
            s_c[tid] = d_au0x[tid];
            s_c[128 + tid] = d_au0t[tid];
            s_c[256 + tid] = b0g[tid];
#pragma unroll
            for (int m = 0; m < 6; m++) s_c[384 + m * 128 + tid] = bMg[m * 128 + tid];
            s_c[1152 + tid] = d_vfin[tid];
        }
        if (tid < 50) {
            s_mlp[tid] = W1[tid]; s_mlp[50 + tid] = b1[tid];
            s_mlp[100 + tid] = b2[tid]; s_mlp[150 + tid] = W3[tid];
        }
        if (tid == 0) s_mlp[2804] = b3[0];
        for (int i = tid; i < 2500; i += 256) {
            const int row = i / 50, col = i % 50;
            s_mlp[200 + row * 52 + col] = W2[i];
        }
        if (tid < 100) s_mlp[200 + (tid >> 1) * 52 + 50 + (tid & 1)] = 0.f;
    }
    __syncthreads();

    // ---- theta MLP: 2 threads per row, float4 W2 reads ----
    {
        const int rl = tid >> 1, hf = tid & 1;
        const float fv = s_fy[rl];
        float h1[52];
        h1[50] = 0.f; h1[51] = 0.f;
#pragma unroll
        for (int j = 0; j < 50; j++) h1[j] = fmaxf(fmaf(s_mlp[j], fv, s_mlp[50 + j]), 0.f);
        float part = 0.f;
        const int j0 = hf * 25;
#pragma unroll 1
        for (int j = j0; j < j0 + 25; j++) {
            const float4* wr = (const float4*)(s_mlp + 200 + j * 52);
            float a0 = s_mlp[100 + j], a1 = 0.f, a2 = 0.f, a3 = 0.f;
#pragma unroll
            for (int k = 0; k < 13; k++) {
                const float4 t4 = wr[k];
                a0 = fmaf(t4.x, h1[4 * k + 0], a0);
                a1 = fmaf(t4.y, h1[4 * k + 1], a1);
                a2 = fmaf(t4.z, h1[4 * k + 2], a2);
                a3 = fmaf(t4.w, h1[4 * k + 3], a3);
            }
            part = fmaf(s_mlp[150 + j], fmaxf((a0 + a1) + (a2 + a3), 0.f), part);
        }
        part += __shfl_xor_sync(~0u, part, 1);
        if (hf == 0) s_th[rl] = part + s_mlp[2804];
    }
    __syncthreads();   // theta done; Apack region free

    // ---- first layer: t0 -> Apack (warp w owns m-tile w) ----
    {
        const int l0 = w * 16 + g, l1 = l0 + 8;
        const float x0 = s_x[l0], x1 = s_x[l1];
        const float t0v = s_th[l0], t1v = s_th[l1];
#pragma unroll
        for (int kp = 0; kp < 8; kp++) {
            const int k0 = kp * 16 + 2 * tig;
            const int k8 = k0 + 8;
            float4 v;
            v.x = sig16x2(0.5f * fmaf(x0, s_c[k0], fmaf(t0v, s_c[128 + k0], s_c[256 + k0])),
                          0.5f * fmaf(x0, s_c[k0 + 1], fmaf(t0v, s_c[128 + k0 + 1], s_c[256 + k0 + 1])));
            v.y = sig16x2(0.5f * fmaf(x1, s_c[k0], fmaf(t1v, s_c[128 + k0], s_c[256 + k0])),
                          0.5f * fmaf(x1, s_c[k0 + 1], fmaf(t1v, s_c[128 + k0 + 1], s_c[256 + k0 + 1])));
            v.z = sig16x2(0.5f * fmaf(x0, s_c[k8], fmaf(t0v, s_c[128 + k8], s_c[256 + k8])),
                          0.5f * fmaf(x0, s_c[k8 + 1], fmaf(t0v, s_c[128 + k8 + 1], s_c[256 + k8 + 1])));
            v.w = sig16x2(0.5f * fmaf(x1, s_c[k8], fmaf(t1v, s_c[128 + k8], s_c[256 + k8])),
                          0.5f * fmaf(x1, s_c[k8 + 1], fmaf(t1v, s_c[128 + k8 + 1], s_c[256 + k8 + 1])));
            a4[(w * 8 + kp) * 32 + lane] = v;
        }
    }
    PAIR_BAR(barid);

    const int mt0 = wm * 2, mt1 = mt0 + 1;

    // ---- 6 GEMM stages, FULLY UNROLLED ----
#pragma unroll
    for (int s = 0; s < NSTAGE; s++) {
        const uint32_t mbF = (s & 1) ? mbF1 : mbF0;
        const uint32_t mbE = (s & 1) ? mbE1 : mbE0;
        const int par = (s >> 1) & 1;
        MBARRIER_WAIT_PARITY(mbF, par);

        float Cacc[2][8][4];
#pragma unroll
        for (int tm = 0; tm < 2; tm++)
#pragma unroll
            for (int t = 0; t < 8; t++) {
                Cacc[tm][t][0] = 0.f; Cacc[tm][t][1] = 0.f;
                Cacc[tm][t][2] = 0.f; Cacc[tm][t][3] = 0.f;
            }

        const float4* wb4 = (const float4*)(dyn + 8192 + (s & 1) * 8192);
#pragma unroll 1
        for (int kph = 0; kph < 4; kph++) {
            const float4 A0a = a4[(mt0 * 8 + 2 * kph) * 32 + lane];
            const float4 A0b = a4[(mt0 * 8 + 2 * kph + 1) * 32 + lane];
            const float4 A1a = a4[(mt1 * 8 + 2 * kph) * 32 + lane];
            const float4 A1b = a4[(mt1 * 8 + 2 * kph + 1) * 32 + lane];
#pragma unroll
            for (int tll = 0; tll < 8; tll++) {
                const float4 bf = wb4[(((wn * 8 + tll) * 4 + kph) * 32) + lane];
                mma16(Cacc[0][tll], A0a, bf.x, bf.y);
                mma16(Cacc[0][tll], A0b, bf.z, bf.w);
                mma16(Cacc[1][tll], A1a, bf.x, bf.y);
                mma16(Cacc[1][tll], A1b, bf.z, bf.w);
            }
        }
        if (lane == 0) MBARRIER_ARRIVE(mbE);   // this warp done reading wbuf(s&1)

        if (s < NSTAGE - 1) {
            PAIR_BAR(barid);   // peer done reading old Apack
            // epilogue: sigmoid(C + bias) as packed f16x2 A-fragments for kp = wn*4+q
            const float* bias = s_c + 384 + s * 128;
#pragma unroll
            for (int tm = 0; tm < 2; tm++) {
                const int mt = mt0 + tm;
#pragma unroll
                for (int q = 0; q < 4; q++) {
                    const int kp = wn * 4 + q;
                    const int n0 = kp * 16 + 2 * tig;
                    const int n1 = n0 + 8;
                    const float hb0 = 0.5f * bias[n0], hb1 = 0.5f * bias[n0 + 1];
                    const float hb2 = 0.5f * bias[n1], hb3 = 0.5f * bias[n1 + 1];
                    float4 v;
                    v.x = sig16x2(fmaf(Cacc[tm][2 * q][0], 0.5f, hb0), fmaf(Cacc[tm][2 * q][1], 0.5f, hb1));
                    v.y = sig16x2(fmaf(Cacc[tm][2 * q][2], 0.5f, hb0), fmaf(Cacc[tm][2 * q][3], 0.5f, hb1));
                    v.z = sig16x2(fmaf(Cacc[tm][2 * q + 1][0], 0.5f, hb2), fmaf(Cacc[tm][2 * q + 1][1], 0.5f, hb3));
                    v.w = sig16x2(fmaf(Cacc[tm][2 * q + 1][2], 0.5f, hb2), fmaf(Cacc[tm][2 * q + 1][3], 0.5f, hb3));
                    a4[(mt * 8 + kp) * 32 + lane] = v;
                }
            }
            PAIR_BAR(barid);   // new Apack visible to peer
            // prefetch AFTER the pair barrier: only warp 0 absorbs the all-warps wait
            if (tid == 0 && s < NSTAGE - 2) {
                MBARRIER_WAIT_PARITY(mbE, par);   // all 8 warps done with wbuf(s&1)
                MBARRIER_EXPECT_TX(mbF, 32768);
                BULK_G2S(dynb + 32768u + (uint32_t)(s & 1) * 32768u, &d_Gpack[s + 2][0], 32768, mbF);
            }
        } else {
            // final: t6 = sigma(C + bM5) in f32; partial dot with v; cross-wn reduce via s_fin
            const float* bias = s_c + 384 + 5 * 128;
            float p[2][2];
            p[0][0] = p[0][1] = p[1][0] = p[1][1] = 0.f;
#pragma unroll
            for (int tm = 0; tm < 2; tm++)
#pragma unroll
                for (int t = 0; t < 8; t++) {
                    const int n0 = wn * 64 + t * 8 + 2 * tig;
                    const float b0v = bias[n0], b1v = bias[n0 + 1];
                    const float v0 = s_c[1152 + n0], v1 = s_c[1152 + n0 + 1];
                    p[tm][0] = fmaf(sigmoid_fast(Cacc[tm][t][0] + b0v), v0, p[tm][0]);
                    p[tm][0] = fmaf(sigmoid_fast(Cacc[tm][t][1] + b1v), v1, p[tm][0]);
                    p[tm][1] = fmaf(sigmoid_fast(Cacc[tm][t][2] + b0v), v0, p[tm][1]);
                    p[tm][1] = fmaf(sigmoid_fast(Cacc[tm][t][3] + b1v), v1, p[tm][1]);
                }
#pragma unroll
            for (int tm = 0; tm < 2; tm++) {
#pragma unroll
                for (int rr = 0; rr < 2; rr++) {
                    p[tm][rr] += __shfl_xor_sync(~0u, p[tm][rr], 1);
                    p[tm][rr] += __shfl_xor_sync(~0u, p[tm][rr], 2);
                }
                if (tig == 0) {
                    const int lr = wm * 32 + tm * 16 + g;
                    s_fin[wn * 128 + lr] = p[tm][0];
                    s_fin[wn * 128 + lr + 8] = p[tm][1];
                }
            }
            __syncthreads();
            if (tid < 128) {
                const int R = blockIdx.x * 128 + tid;
                if (R < n) {
                    const float z = s_fin[tid] + s_fin[128 + tid] + s_c[1280];
                    out[R] = __fdividef(1.0f, 1.0f + __expf(-z));
                }
            }
        }
    }
}

// ===================== launch =====================
extern "C" void kernel_launch(void* const* d_in, const int* in_sizes, int n_in,
                              void* d_out, int out_size) {
    const float* x   = (const float*)d_in[0];
    const float* fy0 = (const float*)d_in[1];
    const float* u0  = (const float*)d_in[2];
    const float* w0  = (const float*)d_in[3];
    const float* la0 = (const float*)d_in[4];
    const float* b0  = (const float*)d_in[5];
    const float* uM  = (const float*)d_in[6];
    const float* wM  = (const float*)d_in[7];
    const float* laM = (const float*)d_in[8];
    const float* bM  = (const float*)d_in[9];
    const float* uL  = (const float*)d_in[10];
    // d_in[11] = wL: softmax of a [1,1] row == 1.0 (identity)
    const float* laL = (const float*)d_in[12];
    const float* bL  = (const float*)d_in[13];
    const float* W1  = (const float*)d_in[14];
    const float* b1  = (const float*)d_in[15];
    const float* W2  = (const float*)d_in[16];
    const float* b2  = (const float*)d_in[17];
    const float* W3  = (const float*)d_in[18];
    const float* b3  = (const float*)d_in[19];
    float* out = (float*)d_out;
    const int n = in_sizes[0];

    const int prep_smem = (16384 + 2048) * 4;   // 73728
    const int fused_smem = 24576 * 4;           // 98304: 32KB Apack + 2x32KB wbuf
    cudaFuncSetAttribute(prep_kernel, cudaFuncAttributeMaxDynamicSharedMemorySize, prep_smem);
    cudaFuncSetAttribute(fused_kernel, cudaFuncAttributeMaxDynamicSharedMemorySize, fused_smem);

    prep_kernel<<<50, 256, prep_smem>>>(u0, w0, la0, uM, wM, laM, uL, laL);
    fused_kernel<<<(n + 127) / 128, 256, fused_smem>>>(x, fy0, b0, bM, bL,
                                                       W1, b1, W2, b2, W3, b3, out, n);
}

// round 17
// speedup vs baseline: 1.2326x; 1.1877x over previous
#include <cuda_runtime.h>
#include <cuda_fp16.h>
#include <math.h>
#include <stdint.h>

#define D 128
#define NSTAGE 6

// ===================== device globals =====================
__device__ __align__(128) __half d_Gpack[NSTAGE][D * D]; // G_m fp16, paired-B-fragment pack
__device__ __align__(16) __half d_W2pack[4096];          // W2 fp16 paired-B pack (64x64 padded)
__device__ float d_au0x[D], d_au0t[D];
__device__ float d_vfin[D];

// ===================== helpers =====================
__device__ __forceinline__ uint32_t smem_u32(const void* p) {
    uint32_t a;
    asm("{ .reg .u64 t; cvta.to.shared.u64 t, %1; cvt.u32.u64 %0, t; }" : "=r"(a) : "l"(p));
    return a;
}
__device__ __forceinline__ float tanh_ap(float x) {
    float y; asm("tanh.approx.f32 %0, %1;" : "=f"(y) : "f"(x)); return y;
}
__device__ __forceinline__ float sigmoid_fast(float x) {
    return fmaf(tanh_ap(0.5f * x), 0.5f, 0.5f);
}
__device__ __forceinline__ float pk2(float lo, float hi) {   // half2{lo,hi} bits as float
    __half2 h = __floats2half2_rn(lo, hi);
    return __uint_as_float(*(uint32_t*)&h);
}
// packed sigmoid: inputs PRE-HALVED z = 0.5*(c + bias); returns half2 {lo,hi} bits
__device__ __forceinline__ float sig16x2(float zlo, float zhi) {
    uint32_t h, t, r;
    asm("cvt.rn.f16x2.f32 %0, %1, %2;" : "=r"(h) : "f"(zhi), "f"(zlo));
    asm("tanh.approx.f16x2 %0, %1;" : "=r"(t) : "r"(h));
    const uint32_t half05 = 0x38003800u;   // half2{0.5, 0.5}
    asm("fma.rn.f16x2 %0, %1, %2, %2;" : "=r"(r) : "r"(t), "r"(half05));
    return __uint_as_float(r);
}

#define MBARRIER_INIT(mbar, count) \
    asm volatile("mbarrier.init.shared.b64 [%0], %1;" :: "r"((uint32_t)(mbar)), "r"((uint32_t)(count)) : "memory")
#define MBARRIER_ARRIVE(mbar) \
    asm volatile("mbarrier.arrive.shared.b64 _, [%0];" :: "r"((uint32_t)(mbar)) : "memory")
#define MBARRIER_EXPECT_TX(mbar, bytes) \
    asm volatile("mbarrier.arrive.expect_tx.shared.b64 _, [%0], %1;" :: "r"((uint32_t)(mbar)), "r"((uint32_t)(bytes)) : "memory")
#define MBARRIER_WAIT_PARITY(mbar, parity) do { \
    uint32_t _m = (uint32_t)(mbar); uint32_t _p = (uint32_t)(parity); uint32_t _d; \
    asm volatile("{\n\t.reg .pred p;\n\t" \
        "mbarrier.try_wait.parity.acquire.cta.shared::cta.b64 p, [%1], %2;\n\t" \
        "selp.b32 %0, 1, 0, p;\n\t}" : "=r"(_d) : "r"(_m), "r"(_p) : "memory"); \
    if (!_d) { \
        asm volatile("{\n\t.reg .pred P1;\n\t" \
            "WAIT_LOOP_%=:\n\t" \
            "mbarrier.try_wait.parity.acquire.cta.shared::cta.b64 P1, [%0], %1, 0x989680;\n\t" \
            "@P1 bra.uni WAIT_DONE_%=;\n\t" \
            "bra.uni WAIT_LOOP_%=;\n\t" \
            "WAIT_DONE_%=:\n\t}" :: "r"(_m), "r"(_p) : "memory"); \
    } \
} while (0)

#define BULK_G2S(smem, gptr, bytes, mbar) \
    asm volatile("cp.async.bulk.shared::cluster.global.mbarrier::complete_tx::bytes [%0], [%1], %2, [%3];" \
        :: "r"((uint32_t)(smem)), "l"(gptr), "r"((uint32_t)(bytes)), "r"((uint32_t)(mbar)) : "memory")

#define PAIR_BAR(id) \
    asm volatile("bar.sync %0, 64;" :: "r"(id) : "memory")

// mma.sync m16n8k16 fp16 -> fp32 accum
__device__ __forceinline__ void mma16(float* d, const float4 a, float b0, float b1) {
    asm volatile(
        "mma.sync.aligned.m16n8k16.row.col.f32.f16.f16.f32 "
        "{%0,%1,%2,%3}, {%4,%5,%6,%7}, {%8,%9}, {%0,%1,%2,%3};"
        : "+f"(d[0]), "+f"(d[1]), "+f"(d[2]), "+f"(d[3])
        : "r"(__float_as_uint(a.x)), "r"(__float_as_uint(a.y)),
          "r"(__float_as_uint(a.z)), "r"(__float_as_uint(a.w)),
          "r"(__float_as_uint(b0)), "r"(__float_as_uint(b1)));
}

// ===================== warp softmax over a 128-row =====================
__device__ __forceinline__ void warp_softmax_row(const float* __restrict__ row,
                                                 float* __restrict__ dst,
                                                 float scale, int lane) {
    float v[4];
#pragma unroll
    for (int q = 0; q < 4; q++) v[q] = row[lane + 32 * q];
    float m = fmaxf(fmaxf(v[0], v[1]), fmaxf(v[2], v[3]));
#pragma unroll
    for (int o = 16; o > 0; o >>= 1) m = fmaxf(m, __shfl_xor_sync(~0u, m, o));
    float e[4]; float s = 0.f;
#pragma unroll
    for (int q = 0; q < 4; q++) { e[q] = __expf(v[q] - m); s += e[q]; }
#pragma unroll
    for (int o = 16; o > 0; o >>= 1) s += __shfl_xor_sync(~0u, s, o);
    const float inv = scale / s;
#pragma unroll
    for (int q = 0; q < 4; q++) dst[lane + 32 * q] = e[q] * inv;
}

// ===================== single prep kernel =====================
__global__ void __launch_bounds__(256) prep_kernel(
    const float* __restrict__ u0, const float* __restrict__ w0,
    const float* __restrict__ la0,
    const float* __restrict__ uM, const float* __restrict__ wM,
    const float* __restrict__ laM,
    const float* __restrict__ uL, const float* __restrict__ laL,
    const float* __restrict__ W2g) {
    extern __shared__ float sh[];   // sW 16384 | sAU 2048
    float* sW = sh;
    float* sAU = sh + 16384;
    const int b = blockIdx.x, tid = threadIdx.x;
    const int w = tid >> 5, lane = tid & 31;

    if (b < 48) {
        const int m = b >> 3;
        const int oc = (b & 7) * 16;
        const float* wsrc = (m == 0) ? w0 : (wM + (m - 1) * D * D);
#pragma unroll 1
        for (int r = w; r < 128; r += 8)
            warp_softmax_row(wsrc + r * D, sW + r * D, 1.0f, lane);
#pragma unroll 1
        for (int rl = w; rl < 16; rl += 8) {
            const int o = oc + rl;
            warp_softmax_row(uM + (m * D + o) * D, sAU + rl * D, __expf(laM[m * D + o]), lane);
        }
        __syncthreads();
#pragma unroll 1
        for (int q = 0; q < 8; q++) {
            const int idx = tid + q * 256;
            const int ol = idx >> 7, i = idx & 127;
            const float* au = sAU + ol * D;
            float acc = 0.f;
#pragma unroll 8
            for (int j = 0; j < D; j++) acc = fmaf(au[j], sW[j * D + i], acc);
            const int o = oc + ol;
            const int t = o >> 3, g = o & 7;
            const int kp = i >> 4, o16 = i & 15;
            const int breg = o16 >> 3, tg = (o16 >> 1) & 3, hl = i & 1;
            const int G = t * 8 + kp;
            const int P = G >> 1, S = G & 1;
            const int L = g * 4 + tg;
            const int hidx = (P * 32 + L) * 8 + S * 4 + breg * 2 + hl;
            d_Gpack[m][hidx] = __float2half_rn(acc);
        }
    } else if (b == 48) {
#pragma unroll 1
        for (int r = w; r < 128; r += 8)
            warp_softmax_row(wM + 5 * D * D + r * D, sW + r * D, 1.0f, lane);
        if (w == 0) warp_softmax_row(uL, sAU, __expf(laL[0]), lane);
        __syncthreads();
        if (tid < D) {
            float acc = 0.f;
#pragma unroll 8
            for (int j = 0; j < D; j++) acc = fmaf(sAU[j], sW[j * D + tid], acc);
            d_vfin[tid] = acc;
        }
    } else if (b == 49) {
        if (tid < D) {
            const int o = tid;
            float v0 = u0[o * 2 + 0], v1 = u0[o * 2 + 1];
            float m = fmaxf(v0, v1);
            float e0 = __expf(v0 - m), e1 = __expf(v1 - m);
            float inv = __expf(la0[o]) / (e0 + e1);
            d_au0x[o] = e0 * inv;
            d_au0t[o] = e1 * inv;
        }
    } else {
        // pack W2 (50x50, zero-padded to 64x64) into fp16 paired-B fragments (4 kp/t)
        for (int idx = tid; idx < 4096; idx += 256) {
            const int o = idx >> 6, i = idx & 63;
            const float val = (o < 50 && i < 50) ? W2g[o * 50 + i] : 0.f;
            const int t = o >> 3, gfrag = o & 7;
            const int kp = i >> 4, o16 = i & 15;
            const int breg = o16 >> 3, tg = (o16 >> 1) & 3, hl = i & 1;
            const int G = t * 4 + kp, P = G >> 1, S = G & 1;
            const int L = gfrag * 4 + tg;
            d_W2pack[(P * 32 + L) * 8 + S * 4 + breg * 2 + hl] = __float2half_rn(val);
        }
    }
}

// ===================== fused kernel =====================
// R16 skeleton; theta's W2 layer moved to tensor cores:
//   h1 A-fragments computed in registers from fy (elementwise), W2 fp16 B-pack from SMEM,
//   C + b2 -> relu -> dot W3 -> pair-reduced into s_th. Zero-pad lanes are inert.
// dyn floats: [0,8192) Apack (W2pack borrows [0,2048) pre-stage-0); [8192,16384) wbuf0;
//             [16384,24576) wbuf1.
__global__ void __launch_bounds__(256, 2) fused_kernel(
    const float* __restrict__ x, const float* __restrict__ fy0,
    const float* __restrict__ b0g, const float* __restrict__ bMg,
    const float* __restrict__ bLg,
    const float* __restrict__ W1, const float* __restrict__ b1,
    const float* __restrict__ b2, const float* __restrict__ W3,
    const float* __restrict__ b3,
    float* __restrict__ out, int n) {
    extern __shared__ float dyn[];
    __shared__ __align__(16) float s_c[1282];     // au0x|au0t|b0|bM[6]|v|bL|b3
    __shared__ __align__(16) float s_mlp2[256];   // W1p|b1p|b2p|W3p (64 each, zero-padded)
    __shared__ float s_x[128], s_fy[128], s_th[128];
    __shared__ float s_fin[256];
    __shared__ __align__(8) unsigned long long s_bar[4];  // full0, full1, empty0, empty1

    const int tid = threadIdx.x;
    const int w = tid >> 5, lane = tid & 31;
    const int g = lane >> 2, tig = lane & 3;
    const int wm = w >> 1, wn = w & 1;
    const int barid = 1 + wm;
    const uint32_t mbF0 = smem_u32(&s_bar[0]);
    const uint32_t mbF1 = smem_u32(&s_bar[1]);
    const uint32_t mbE0 = smem_u32(&s_bar[2]);
    const uint32_t mbE1 = smem_u32(&s_bar[3]);
    const uint32_t dynb = smem_u32(dyn);

    float4* a4 = (float4*)dyn;      // 2048 float4 = 32KB Apack

    if (tid == 0) {
        MBARRIER_INIT(mbF0, 1); MBARRIER_INIT(mbF1, 1);
        MBARRIER_INIT(mbE0, 8); MBARRIER_INIT(mbE1, 8);
        MBARRIER_EXPECT_TX(mbF0, 32768);
        BULK_G2S(dynb + 32768u, &d_Gpack[0][0], 32768, mbF0);
        MBARRIER_EXPECT_TX(mbF1, 32768);
        BULK_G2S(dynb + 65536u, &d_Gpack[1][0], 32768, mbF1);
        s_c[1280] = bLg[0];
        s_c[1281] = b3[0];
    }
    {
        const int gi = blockIdx.x * 128 + tid;
        if (tid < 128) {
            const bool ok = gi < n;
            s_x[tid] = ok ? x[gi] : 0.f;
            s_fy[tid] = ok ? fy0[gi] : 0.f;
            s_c[tid] = d_au0x[tid];
            s_c[128 + tid] = d_au0t[tid];
            s_c[256 + tid] = b0g[tid];
#pragma unroll
            for (int m = 0; m < 6; m++) s_c[384 + m * 128 + tid] = bMg[m * 128 + tid];
            s_c[1152 + tid] = d_vfin[tid];
        }
        if (tid < 64) {
            const bool ok = tid < 50;
            s_mlp2[tid]       = ok ? W1[tid] : 0.f;
            s_mlp2[64 + tid]  = ok ? b1[tid] : 0.f;
            s_mlp2[128 + tid] = ok ? b2[tid] : 0.f;
            s_mlp2[192 + tid] = ok ? W3[tid] : 0.f;
        }
        // W2pack fp16 fragments into Apack region [0,2048) floats
        for (int i = tid; i < 2048; i += 256) dyn[i] = ((const float*)d_W2pack)[i];
    }
    __syncthreads();

    // ---- theta: h2 = relu(W2 h1 + b2) via tensor cores; theta = W3.h2' + b3 ----
    {
        const float* W1p = s_mlp2;
        const float* b1p = s_mlp2 + 64;
        float Ct[2][4][4];
#pragma unroll
        for (int tm = 0; tm < 2; tm++)
#pragma unroll
            for (int t = 0; t < 4; t++) {
                Ct[tm][t][0] = 0.f; Ct[tm][t][1] = 0.f; Ct[tm][t][2] = 0.f; Ct[tm][t][3] = 0.f;
            }
        const float4* w2b = (const float4*)dyn;   // 512 float4
#pragma unroll
        for (int kph = 0; kph < 2; kph++) {
            float4 Af[2][2];
#pragma unroll
            for (int tm = 0; tm < 2; tm++) {
                const int r0 = (wm * 2 + tm) * 16 + g, r1 = r0 + 8;
                const float f0 = s_fy[r0], f1 = s_fy[r1];
#pragma unroll
                for (int kq = 0; kq < 2; kq++) {
                    const int k0 = (kph * 2 + kq) * 16 + 2 * tig;
                    const int k8 = k0 + 8;
                    float4 v;
                    v.x = pk2(fmaxf(fmaf(W1p[k0], f0, b1p[k0]), 0.f),
                              fmaxf(fmaf(W1p[k0 + 1], f0, b1p[k0 + 1]), 0.f));
                    v.y = pk2(fmaxf(fmaf(W1p[k0], f1, b1p[k0]), 0.f),
                              fmaxf(fmaf(W1p[k0 + 1], f1, b1p[k0 + 1]), 0.f));
                    v.z = pk2(fmaxf(fmaf(W1p[k8], f0, b1p[k8]), 0.f),
                              fmaxf(fmaf(W1p[k8 + 1], f0, b1p[k8 + 1]), 0.f));
                    v.w = pk2(fmaxf(fmaf(W1p[k8], f1, b1p[k8]), 0.f),
                              fmaxf(fmaf(W1p[k8 + 1], f1, b1p[k8 + 1]), 0.f));
                    Af[tm][kq] = v;
                }
            }
#pragma unroll
            for (int tll = 0; tll < 4; tll++) {
                const int t = wn * 4 + tll;
                const float4 bf = w2b[(t * 2 + kph) * 32 + lane];
                mma16(Ct[0][tll], Af[0][0], bf.x, bf.y);
                mma16(Ct[0][tll], Af[0][1], bf.z, bf.w);
                mma16(Ct[1][tll], Af[1][0], bf.x, bf.y);
                mma16(Ct[1][tll], Af[1][1], bf.z, bf.w);
            }
        }
        float p[2][2];
        p[0][0] = p[0][1] = p[1][0] = p[1][1] = 0.f;
#pragma unroll
        for (int tm = 0; tm < 2; tm++)
#pragma unroll
            for (int tll = 0; tll < 4; tll++) {
                const int n0 = (wn * 4 + tll) * 8 + 2 * tig;
                const float w30 = s_mlp2[192 + n0], w31 = s_mlp2[192 + n0 + 1];
                const float bb0 = s_mlp2[128 + n0], bb1 = s_mlp2[128 + n0 + 1];
                p[tm][0] = fmaf(fmaxf(Ct[tm][tll][0] + bb0, 0.f), w30, p[tm][0]);
                p[tm][0] = fmaf(fmaxf(Ct[tm][tll][1] + bb1, 0.f), w31, p[tm][0]);
                p[tm][1] = fmaf(fmaxf(Ct[tm][tll][2] + bb0, 0.f), w30, p[tm][1]);
                p[tm][1] = fmaf(fmaxf(Ct[tm][tll][3] + bb1, 0.f), w31, p[tm][1]);
            }
#pragma unroll
        for (int tm = 0; tm < 2; tm++) {
#pragma unroll
            for (int rr = 0; rr < 2; rr++) {
                p[tm][rr] += __shfl_xor_sync(~0u, p[tm][rr], 1);
                p[tm][rr] += __shfl_xor_sync(~0u, p[tm][rr], 2);
            }
            if (tig == 0) {
                const int lr = wm * 32 + tm * 16 + g;
                s_fin[wn * 128 + lr] = p[tm][0];
                s_fin[wn * 128 + lr + 8] = p[tm][1];
            }
        }
        PAIR_BAR(barid);
        if (wn == 0) {
            const int lr = wm * 32 + lane;
            s_th[lr] = s_fin[lr] + s_fin[128 + lr] + s_c[1281];
        }
    }
    __syncthreads();   // s_th visible; W2pack region free for A-fragments

    // ---- first layer: t0 -> Apack (warp w owns m-tile w) ----
    {
        const int l0 = w * 16 + g, l1 = l0 + 8;
        const float x0 = s_x[l0], x1 = s_x[l1];
        const float t0v = s_th[l0], t1v = s_th[l1];
#pragma unroll
        for (int kp = 0; kp < 8; kp++) {
            const int k0 = kp * 16 + 2 * tig;
            const int k8 = k0 + 8;
            float4 v;
            v.x = sig16x2(0.5f * fmaf(x0, s_c[k0], fmaf(t0v, s_c[128 + k0], s_c[256 + k0])),
                          0.5f * fmaf(x0, s_c[k0 + 1], fmaf(t0v, s_c[128 + k0 + 1], s_c[256 + k0 + 1])));
            v.y = sig16x2(0.5f * fmaf(x1, s_c[k0], fmaf(t1v, s_c[128 + k0], s_c[256 + k0])),
                          0.5f * fmaf(x1, s_c[k0 + 1], fmaf(t1v, s_c[128 + k0 + 1], s_c[256 + k0 + 1])));
            v.z = sig16x2(0.5f * fmaf(x0, s_c[k8], fmaf(t0v, s_c[128 + k8], s_c[256 + k8])),
                          0.5f * fmaf(x0, s_c[k8 + 1], fmaf(t0v, s_c[128 + k8 + 1], s_c[256 + k8 + 1])));
            v.w = sig16x2(0.5f * fmaf(x1, s_c[k8], fmaf(t1v, s_c[128 + k8], s_c[256 + k8])),
                          0.5f * fmaf(x1, s_c[k8 + 1], fmaf(t1v, s_c[128 + k8 + 1], s_c[256 + k8 + 1])));
            a4[(w * 8 + kp) * 32 + lane] = v;
        }
    }
    PAIR_BAR(barid);

    const int mt0 = wm * 2, mt1 = mt0 + 1;

    // ---- 6 GEMM stages, fully unrolled ----
#pragma unroll
    for (int s = 0; s < NSTAGE; s++) {
        const uint32_t mbF = (s & 1) ? mbF1 : mbF0;
        const uint32_t mbE = (s & 1) ? mbE1 : mbE0;
        const int par = (s >> 1) & 1;
        MBARRIER_WAIT_PARITY(mbF, par);

        float Cacc[2][8][4];
#pragma unroll
        for (int tm = 0; tm < 2; tm++)
#pragma unroll
            for (int t = 0; t < 8; t++) {
                Cacc[tm][t][0] = 0.f; Cacc[tm][t][1] = 0.f;
                Cacc[tm][t][2] = 0.f; Cacc[tm][t][3] = 0.f;
            }

        const float4* wb4 = (const float4*)(dyn + 8192 + (s & 1) * 8192);
#pragma unroll 1
        for (int kph = 0; kph < 4; kph++) {
            const float4 A0a = a4[(mt0 * 8 + 2 * kph) * 32 + lane];
            const float4 A0b = a4[(mt0 * 8 + 2 * kph + 1) * 32 + lane];
            const float4 A1a = a4[(mt1 * 8 + 2 * kph) * 32 + lane];
            const float4 A1b = a4[(mt1 * 8 + 2 * kph + 1) * 32 + lane];
#pragma unroll
            for (int tll = 0; tll < 8; tll++) {
                const float4 bf = wb4[(((wn * 8 + tll) * 4 + kph) * 32) + lane];
                mma16(Cacc[0][tll], A0a, bf.x, bf.y);
                mma16(Cacc[0][tll], A0b, bf.z, bf.w);
                mma16(Cacc[1][tll], A1a, bf.x, bf.y);
                mma16(Cacc[1][tll], A1b, bf.z, bf.w);
            }
        }
        if (lane == 0) MBARRIER_ARRIVE(mbE);

        if (s < NSTAGE - 1) {
            PAIR_BAR(barid);
            const float* bias = s_c + 384 + s * 128;
#pragma unroll
            for (int tm = 0; tm < 2; tm++) {
                const int mt = mt0 + tm;
#pragma unroll
                for (int q = 0; q < 4; q++) {
                    const int kp = wn * 4 + q;
                    const int n0 = kp * 16 + 2 * tig;
                    const int n1 = n0 + 8;
                    const float hb0 = 0.5f * bias[n0], hb1 = 0.5f * bias[n0 + 1];
                    const float hb2 = 0.5f * bias[n1], hb3 = 0.5f * bias[n1 + 1];
                    float4 v;
                    v.x = sig16x2(fmaf(Cacc[tm][2 * q][0], 0.5f, hb0), fmaf(Cacc[tm][2 * q][1], 0.5f, hb1));
                    v.y = sig16x2(fmaf(Cacc[tm][2 * q][2], 0.5f, hb0), fmaf(Cacc[tm][2 * q][3], 0.5f, hb1));
                    v.z = sig16x2(fmaf(Cacc[tm][2 * q + 1][0], 0.5f, hb2), fmaf(Cacc[tm][2 * q + 1][1], 0.5f, hb3));
                    v.w = sig16x2(fmaf(Cacc[tm][2 * q + 1][2], 0.5f, hb2), fmaf(Cacc[tm][2 * q + 1][3], 0.5f, hb3));
                    a4[(mt * 8 + kp) * 32 + lane] = v;
                }
            }
            PAIR_BAR(barid);
            if (tid == 0 && s < NSTAGE - 2) {
                MBARRIER_WAIT_PARITY(mbE, par);
                MBARRIER_EXPECT_TX(mbF, 32768);
                BULK_G2S(dynb + 32768u + (uint32_t)(s & 1) * 32768u, &d_Gpack[s + 2][0], 32768, mbF);
            }
        } else {
            const float* bias = s_c + 384 + 5 * 128;
            float p[2][2];
            p[0][0] = p[0][1] = p[1][0] = p[1][1] = 0.f;
#pragma unroll
            for (int tm = 0; tm < 2; tm++)
#pragma unroll
                for (int t = 0; t < 8; t++) {
                    const int n0 = wn * 64 + t * 8 + 2 * tig;
                    const float b0v = bias[n0], b1v = bias[n0 + 1];
                    const float v0 = s_c[1152 + n0], v1 = s_c[1152 + n0 + 1];
                    p[tm][0] = fmaf(sigmoid_fast(Cacc[tm][t][0] + b0v), v0, p[tm][0]);
                    p[tm][0] = fmaf(sigmoid_fast(Cacc[tm][t][1] + b1v), v1, p[tm][0]);
                    p[tm][1] = fmaf(sigmoid_fast(Cacc[tm][t][2] + b0v), v0, p[tm][1]);
                    p[tm][1] = fmaf(sigmoid_fast(Cacc[tm][t][3] + b1v), v1, p[tm][1]);
                }
#pragma unroll
            for (int tm = 0; tm < 2; tm++) {
#pragma unroll
                for (int rr = 0; rr < 2; rr++) {
                    p[tm][rr] += __shfl_xor_sync(~0u, p[tm][rr], 1);
                    p[tm][rr] += __shfl_xor_sync(~0u, p[tm][rr], 2);
                }
                if (tig == 0) {
                    const int lr = wm * 32 + tm * 16 + g;
                    s_fin[wn * 128 + lr] = p[tm][0];
                    s_fin[wn * 128 + lr + 8] = p[tm][1];
                }
            }
            __syncthreads();
            if (tid < 128) {
                const int R = blockIdx.x * 128 + tid;
                if (R < n) {
                    const float z = s_fin[tid] + s_fin[128 + tid] + s_c[1280];
                    out[R] = __fdividef(1.0f, 1.0f + __expf(-z));
                }
            }
        }
    }
}

// ===================== launch =====================
extern "C" void kernel_launch(void* const* d_in, const int* in_sizes, int n_in,
                              void* d_out, int out_size) {
    const float* x   = (const float*)d_in[0];
    const float* fy0 = (const float*)d_in[1];
    const float* u0  = (const float*)d_in[2];
    const float* w0  = (const float*)d_in[3];
    const float* la0 = (const float*)d_in[4];
    const float* b0  = (const float*)d_in[5];
    const float* uM  = (const float*)d_in[6];
    const float* wM  = (const float*)d_in[7];
    const float* laM = (const float*)d_in[8];
    const float* bM  = (const float*)d_in[9];
    const float* uL  = (const float*)d_in[10];
    // d_in[11] = wL: softmax of a [1,1] row == 1.0 (identity)
    const float* laL = (const float*)d_in[12];
    const float* bL  = (const float*)d_in[13];
    const float* W1  = (const float*)d_in[14];
    const float* b1  = (const float*)d_in[15];
    const float* W2  = (const float*)d_in[16];
    const float* b2  = (const float*)d_in[17];
    const float* W3  = (const float*)d_in[18];
    const float* b3  = (const float*)d_in[19];
    float* out = (float*)d_out;
    const int n = in_sizes[0];

    const int prep_smem = (16384 + 2048) * 4;   // 73728
    const int fused_smem = 24576 * 4;           // 98304: 32KB Apack + 2x32KB wbuf
    cudaFuncSetAttribute(prep_kernel, cudaFuncAttributeMaxDynamicSharedMemorySize, prep_smem);
    cudaFuncSetAttribute(fused_kernel, cudaFuncAttributeMaxDynamicSharedMemorySize, fused_smem);

    prep_kernel<<<51, 256, prep_smem>>>(u0, w0, la0, uM, wM, laM, uL, laL, W2);
    fused_kernel<<<(n + 127) / 128, 256, fused_smem>>>(x, fy0, b0, bM, bL,
                                                       W1, b1, b2, W3, b3, out, n);
}